// round 15
// baseline (speedup 1.0000x reference)
#include <cuda_runtime.h>
#include <cuda_bf16.h>
#include <cuda_fp16.h>
#include <stdint.h>

constexpr int M_ = 4096;     // batch B
constexpr int K_ = 2048;     // D
constexpr int N_ = 16384;    // L
constexpr int TOPK = 64;
constexpr float MARGIN = 0.036f;  // > 2*(8*sigma_gemm + fp16 half-ulp) = 2*0.015
constexpr int CANDCAP = 192;

// ---------------- scratch (device globals; no allocs allowed) ----------------
__device__ __align__(256) __nv_bfloat16 g_xhi[M_ * K_];
__device__ __align__(256) __nv_bfloat16 g_whiT[(size_t)N_ * K_];  // W_enc^T bf16 [N,K]
__device__ __align__(256) float g_wT[(size_t)N_ * K_];            // W_enc^T fp32 [N,K]
__device__ __align__(256) __half g_zh[(size_t)M_ * N_];           // approx z, fp16
__device__ float g_topv[M_ * TOPK];
__device__ int   g_topi[M_ * TOPK];
__device__ int   g_cand[M_ * CANDCAP];   // idx | (above << 31)
__device__ int   g_ncand[M_];
__device__ int   g_nabove[M_];

// ---------------- helpers (family-safe ISA: sm_80/90 base) ----------------
__device__ __forceinline__ uint32_t smem_u32(const void* p) {
    uint32_t a;
    asm("{ .reg .u64 t; cvta.to.shared.u64 t, %1; cvt.u32.u64 %0, t; }" : "=r"(a) : "l"(p));
    return a;
}
__device__ __forceinline__ void cp_async16(uint32_t s, const void* g) {
    asm volatile("cp.async.cg.shared.global [%0], [%1], 16;" :: "r"(s), "l"(g));
}
__device__ __forceinline__ void ldmatrix4(uint32_t* r, uint32_t addr) {
    asm volatile("ldmatrix.sync.aligned.m8n8.x4.shared.b16 {%0,%1,%2,%3}, [%4];"
                 : "=r"(r[0]), "=r"(r[1]), "=r"(r[2]), "=r"(r[3]) : "r"(addr));
}
__device__ __forceinline__ void mma16816(float* d, const uint32_t* a, uint32_t b0, uint32_t b1) {
    asm volatile(
        "mma.sync.aligned.m16n8k16.row.col.f32.bf16.bf16.f32 "
        "{%0,%1,%2,%3}, {%4,%5,%6,%7}, {%8,%9}, {%0,%1,%2,%3};"
        : "+f"(d[0]), "+f"(d[1]), "+f"(d[2]), "+f"(d[3])
        : "r"(a[0]), "r"(a[1]), "r"(a[2]), "r"(a[3]), "r"(b0), "r"(b1));
}

// ---------------- conversion kernels ----------------
__global__ void __launch_bounds__(256) conv_x_kernel(const float* __restrict__ x) {
    int i = blockIdx.x * 256 + threadIdx.x;
    if (i < M_ * K_) g_xhi[i] = __float2bfloat16(x[i]);
}

// W_enc [K,N] -> transposed [N,K]: bf16 + fp32 copies
__global__ void __launch_bounds__(256) conv_w_kernel(const float* __restrict__ W) {
    __shared__ float t[32][33];
    const int tx = threadIdx.x, ty = threadIdx.y;   // 32 x 8
    const int n0 = blockIdx.x * 32, k0 = blockIdx.y * 32;
    #pragma unroll
    for (int j = 0; j < 4; j++)
        t[ty + j * 8][tx] = W[(size_t)(k0 + ty + j * 8) * N_ + (n0 + tx)];
    __syncthreads();
    #pragma unroll
    for (int j = 0; j < 4; j++) {
        float v = t[tx][ty + j * 8];
        size_t o = (size_t)(n0 + ty + j * 8) * K_ + (k0 + tx);
        g_whiT[o] = __float2bfloat16(v);
        g_wT[o] = v;
    }
}

// ---------------- bf16 encode GEMM: BK=64, 3-stage, ONE sync per chunk ----------------
constexpr int BK = 64;
constexpr int ROWB = 144;               // 64 bf16 = 128B + 16B pad (conflict-free ldmatrix)
constexpr int TILEB = 128 * ROWB;       // 18432 B
constexpr int STAGEB = 2 * TILEB;       // 36864 B (A+B)
constexpr int NSTAGE = 3;
constexpr int GEMM_SMEM = NSTAGE * STAGEB;   // 110592 B (2 CTAs/SM)

__global__ void __launch_bounds__(256, 2) enc_gemm_mma(const float* __restrict__ b_enc) {
    extern __shared__ char sm[];
    const uint32_t base = smem_u32(sm);
    const int tid = threadIdx.x, lane = tid & 31, wid = tid >> 5;
    const int wm = wid & 3, wn = wid >> 2;          // 4x2 warp grid, warp tile 32x64
    const int row0 = blockIdx.x * 128;              // M tile
    const int col0 = blockIdx.y * 128;              // N tile

    float c[2][8][4];
    #pragma unroll
    for (int i = 0; i < 2; i++)
        #pragma unroll
        for (int j = 0; j < 8; j++)
            #pragma unroll
            for (int q = 0; q < 4; q++) c[i][j][q] = 0.f;

    auto issue = [&](int ch) {
        const int kk = ch * BK;
        const uint32_t st = base + (ch % NSTAGE) * STAGEB;
        #pragma unroll
        for (int j = 0; j < 4; j++) {
            const int slot = tid + 256 * j;         // 0..1023
            const int r = slot >> 3, cc = slot & 7; // 128 rows x 8 x 16B
            cp_async16(st + r * ROWB + cc * 16,
                       g_xhi + (size_t)(row0 + r) * K_ + kk + cc * 8);
            cp_async16(st + TILEB + r * ROWB + cc * 16,
                       g_whiT + (size_t)(col0 + r) * K_ + kk + cc * 8);
        }
        asm volatile("cp.async.commit_group;");
    };

    auto compute = [&](int s) {
        const uint32_t sa = base + s * STAGEB;
        const uint32_t sb = sa + TILEB;
        #pragma unroll
        for (int ks = 0; ks < 4; ks++) {
            uint32_t a[2][4];
            #pragma unroll
            for (int mi = 0; mi < 2; mi++) {
                const int row = wm * 32 + mi * 16 + (lane & 15);
                ldmatrix4(a[mi], sa + row * ROWB + ks * 32 + ((lane >> 4) << 4));
            }
            uint32_t b[4][4];
            #pragma unroll
            for (int nl = 0; nl < 4; nl++) {
                const int row = wn * 64 + nl * 16 + (lane & 7) + ((lane >> 4) << 3);
                ldmatrix4(b[nl], sb + row * ROWB + ks * 32 + (((lane >> 3) & 1) << 4));
            }
            #pragma unroll
            for (int mi = 0; mi < 2; mi++)
                #pragma unroll
                for (int nl = 0; nl < 4; nl++) {
                    mma16816(c[mi][2 * nl + 0], a[mi], b[nl][0], b[nl][1]);
                    mma16816(c[mi][2 * nl + 1], a[mi], b[nl][2], b[nl][3]);
                }
        }
    };

    constexpr int NCH = K_ / BK;        // 32
    issue(0); issue(1);                 // prologue: 2 chunks in flight
    for (int i = 0; i < NCH; i++) {
        asm volatile("cp.async.wait_group 1;");     // chunk i resident
        __syncthreads();                            // all warps done with stage (i-1)%3
        if (i + 2 < NCH) issue(i + 2);              // refill stage (i-1)%3
        else asm volatile("cp.async.commit_group;");// keep group-count math valid
        compute(i % NSTAGE);
    }

    const int gid = lane >> 2, tig = lane & 3;
    #pragma unroll
    for (int mi = 0; mi < 2; mi++) {
        const int r0 = row0 + wm * 32 + mi * 16 + gid;
        #pragma unroll
        for (int ni = 0; ni < 8; ni++) {
            const int cc = col0 + wn * 64 + ni * 8 + 2 * tig;
            const float2 bb = *(const float2*)(b_enc + cc);
            __half2 h0 = __floats2half2_rn(c[mi][ni][0] + bb.x, c[mi][ni][1] + bb.y);
            __half2 h1 = __floats2half2_rn(c[mi][ni][2] + bb.x, c[mi][ni][3] + bb.y);
            *(__half2*)(g_zh + (size_t)r0 * N_ + cc) = h0;
            *(__half2*)(g_zh + (size_t)(r0 + 8) * N_ + cc) = h1;
        }
    }
}

// ---------------- top-k on fp16 keys: 2-pass radix + candidate emit ----------------
__global__ void __launch_bounds__(256) topk_h_kernel() {
    __shared__ uint32_t skey[N_ / 2];        // 8192 words, 2 keys each (32KB)
    __shared__ int hist[8][256];             // per-warp histograms (8KB)
    __shared__ int s_h1[256];
    __shared__ int s_b, s_r, s_T;
    __shared__ int s_nc, s_na;

    const int row = blockIdx.x;
    const int tid = threadIdx.x, wid = tid >> 5, lane = tid & 31;

    for (int b = tid; b < 8 * 256; b += 256) ((int*)hist)[b] = 0;
    if (tid == 0) { s_nc = 0; s_na = 0; }
    __syncthreads();

    // warp-aggregated histogram add: one atomic per distinct bucket per warp
    auto hist_add = [&](uint32_t bucket) {
        unsigned m = __match_any_sync(0xFFFFFFFFu, bucket);
        if ((unsigned)(__ffs(m) - 1) == (unsigned)lane)
            atomicAdd(&hist[wid][bucket], __popc(m));
    };

    // pass 0: load row (2048 uint4), pack 15-bit keys, hist on top 8 bits
    const uint4* zr = (const uint4*)(g_zh + (size_t)row * N_);
    #pragma unroll
    for (int it = 0; it < 8; it++) {
        const int i4 = tid + it * 256;        // uint4 index: 8 fp16 each
        uint4 v = zr[i4];
        uint32_t wv[4] = { v.x, v.y, v.z, v.w };
        #pragma unroll
        for (int q = 0; q < 4; q++) {
            uint32_t lo = wv[q] & 0x7FFFu;
            uint32_t hi = (wv[q] >> 16) & 0x7FFFu;
            skey[i4 * 4 + q] = lo | (hi << 16);   // word w holds elements 2w, 2w+1
            hist_add(lo >> 7);
            hist_add(hi >> 7);
        }
    }
    __syncthreads();
    {
        int tot = 0;
        #pragma unroll
        for (int w = 0; w < 8; w++) tot += hist[w][tid];
        s_h1[tid] = tot;
    }
    __syncthreads();
    if (tid == 0) {
        int r = TOPK, b = 255;
        for (; b > 0; b--) { int cnt = s_h1[b]; if (cnt >= r) break; r -= cnt; }
        s_b = b; s_r = r;
    }
    __syncthreads();
    const int bsel = s_b;

    // pass 1: hist on low 7 bits within bucket bsel (all 8192 words)
    for (int b = tid; b < 8 * 256; b += 256) ((int*)hist)[b] = 0;
    __syncthreads();
    #pragma unroll
    for (int it = 0; it < 32; it++) {
        const int iw = tid + it * 256;        // 0..8191
        uint32_t pk = skey[iw];
        uint32_t lo = pk & 0xFFFFu, hi = pk >> 16;
        if ((int)(lo >> 7) == bsel) atomicAdd(&hist[wid][lo & 127u], 1);
        if ((int)(hi >> 7) == bsel) atomicAdd(&hist[wid][hi & 127u], 1);
    }
    __syncthreads();
    if (tid < 128) {
        int tot = 0;
        #pragma unroll
        for (int w = 0; w < 8; w++) tot += hist[w][tid];
        s_h1[tid] = tot;
    }
    __syncthreads();
    if (tid == 0) {
        int r = s_r, m = 127;
        for (; m > 0; m--) { int cnt = s_h1[m]; if (cnt >= r) break; r -= cnt; }
        s_T = (bsel << 7) | m;
    }
    __syncthreads();

    // fp16 threshold bits -> float (exact)
    __half_raw traw; traw.x = (unsigned short)s_T;
    const float tval = __half2float(__half(traw));
    const float blo = tval - MARGIN, bhi = tval + MARGIN;

    // pass 2: count above-band, emit candidates (|z| >= blo) over all 8192 words
    int myabove = 0;
    #pragma unroll
    for (int it = 0; it < 32; it++) {
        const int iw = tid + it * 256;        // 0..8191
        uint32_t pk = skey[iw];
        #pragma unroll
        for (int h = 0; h < 2; h++) {
            uint32_t key = h ? (pk >> 16) : (pk & 0xFFFFu);
            __half_raw kr; kr.x = (unsigned short)key;
            float av = __half2float(__half(kr));
            if (av >= blo) {
                bool above = (av > bhi);
                myabove += above ? 1 : 0;
                int p = atomicAdd(&s_nc, 1);
                if (p < CANDCAP)
                    g_cand[row * CANDCAP + p] = (iw * 2 + h) | (above ? 0x80000000 : 0);
            }
        }
    }
    atomicAdd(&s_na, myabove);
    __syncthreads();
    if (tid == 0) {
        g_ncand[row] = min(s_nc, CANDCAP);
        g_nabove[row] = s_na;
    }
}

// ---------------- exact fixup: fp32 dots, exact re-rank, scatter into zeroed z ----------------
__global__ void __launch_bounds__(256) fixup_kernel(
    const float* __restrict__ x, const float* __restrict__ b_enc,
    float* __restrict__ z) {
    __shared__ float sx[K_];
    __shared__ int   s_idx[CANDCAP];
    __shared__ float s_val[CANDCAP];
    __shared__ unsigned char s_abv[CANDCAP];
    __shared__ unsigned char s_keep[CANDCAP];

    const int row = blockIdx.x;
    const int tid = threadIdx.x, lid = tid & 31, wrp = tid >> 5;
    const int nc = g_ncand[row];
    const int slots = TOPK - g_nabove[row];

    for (int i = tid; i < K_; i += 256) sx[i] = x[(size_t)row * K_ + i];
    if (tid < nc) {
        int e = g_cand[row * CANDCAP + tid];
        s_idx[tid] = e & 0x7FFFFFFF;
        s_abv[tid] = (e >> 31) & 1;
        s_keep[tid] = 0;
    }
    __syncthreads();

    // exact fp32 dots against coalesced g_wT rows
    for (int c = wrp; c < nc; c += 8) {
        const int j = s_idx[c];
        const float* wr = g_wT + (size_t)j * K_;
        float a0 = 0.f, a1 = 0.f, a2 = 0.f, a3 = 0.f;
        for (int k = lid; k < K_; k += 128) {
            a0 = fmaf(sx[k],      wr[k],      a0);
            a1 = fmaf(sx[k + 32], wr[k + 32], a1);
            a2 = fmaf(sx[k + 64], wr[k + 64], a2);
            a3 = fmaf(sx[k + 96], wr[k + 96], a3);
        }
        float acc = (a0 + a1) + (a2 + a3);
        #pragma unroll
        for (int o = 16; o; o >>= 1) acc += __shfl_xor_sync(0xFFFFFFFFu, acc, o);
        if (lid == 0) s_val[c] = acc + b_enc[j];
    }
    __syncthreads();

    // keep: all above-band + top-`slots` band members by (|exact|, idx)
    if (tid < nc) {
        if (s_abv[tid]) {
            s_keep[tid] = 1;
        } else {
            const float mv = fabsf(s_val[tid]);
            const int mi = s_idx[tid];
            int rank = 0;
            for (int f = 0; f < nc; f++) {
                if (s_abv[f] || f == tid) continue;
                const float fv = fabsf(s_val[f]);
                if (fv > mv || (fv == mv && s_idx[f] < mi)) rank++;
            }
            s_keep[tid] = (rank < slots) ? 1 : 0;
        }
    }
    __syncthreads();

    // scatter exact kept values into zeroed z + final compact lists (index-ascending)
    float* zrow = z + (size_t)row * N_;
    if (tid < nc && s_keep[tid]) {
        const int mi = s_idx[tid];
        zrow[mi] = s_val[tid];
        int pos = 0;
        for (int f = 0; f < nc; f++)
            if (s_keep[f] && s_idx[f] < mi) pos++;
        if (pos < TOPK) {
            g_topv[row * TOPK + pos] = s_val[tid];
            g_topi[row * TOPK + pos] = mi;
        }
    }
}

// ---------------- sparse decode: 2 CTAs per row (half-row each) ----------------
__global__ void __launch_bounds__(256) dec_kernel(
    const float* __restrict__ Wd, const float* __restrict__ bd,
    float* __restrict__ recon) {
    __shared__ float sv[TOPK];
    __shared__ int   si[TOPK];
    const int row = blockIdx.x;
    const int tid = threadIdx.x;
    if (tid < TOPK) { sv[tid] = g_topv[row * TOPK + tid]; si[tid] = g_topi[row * TOPK + tid]; }
    __syncthreads();

    const int c0 = blockIdx.y * 1024 + tid * 4;   // this CTA's half-row column
    float4 a0 = *(const float4*)(bd + c0);
    #pragma unroll 4
    for (int j = 0; j < TOPK; j += 4) {
        const float v0 = sv[j], v1 = sv[j + 1], v2 = sv[j + 2], v3 = sv[j + 3];
        float4 w0 = *(const float4*)(Wd + (size_t)si[j] * 2048 + c0);
        float4 w1 = *(const float4*)(Wd + (size_t)si[j + 1] * 2048 + c0);
        float4 w2 = *(const float4*)(Wd + (size_t)si[j + 2] * 2048 + c0);
        float4 w3 = *(const float4*)(Wd + (size_t)si[j + 3] * 2048 + c0);
        a0.x += v0 * w0.x; a0.y += v0 * w0.y; a0.z += v0 * w0.z; a0.w += v0 * w0.w;
        a0.x += v1 * w1.x; a0.y += v1 * w1.y; a0.z += v1 * w1.z; a0.w += v1 * w1.w;
        a0.x += v2 * w2.x; a0.y += v2 * w2.y; a0.z += v2 * w2.z; a0.w += v2 * w2.w;
        a0.x += v3 * w3.x; a0.y += v3 * w3.y; a0.z += v3 * w3.z; a0.w += v3 * w3.w;
    }
    *(float4*)(recon + (size_t)row * 2048 + c0) = a0;
}

// ---------------- launch ----------------
extern "C" void kernel_launch(void* const* d_in, const int* in_sizes, int n_in,
                              void* d_out, int out_size) {
    const float* x     = (const float*)d_in[0];
    const float* W_enc = (const float*)d_in[1];
    const float* b_enc = (const float*)d_in[2];
    const float* W_dec = (const float*)d_in[3];
    const float* b_dec = (const float*)d_in[4];

    float* recon = (float*)d_out;
    float* zsp   = (float*)d_out + (size_t)M_ * 2048;

    cudaFuncSetAttribute(enc_gemm_mma, cudaFuncAttributeMaxDynamicSharedMemorySize, GEMM_SMEM);

    cudaMemsetAsync(zsp, 0, (size_t)M_ * N_ * sizeof(float));
    conv_x_kernel<<<(M_ * K_ + 255) / 256, 256>>>(x);
    conv_w_kernel<<<dim3(N_ / 32, K_ / 32), dim3(32, 8)>>>(W_enc);
    enc_gemm_mma<<<dim3(M_ / 128, N_ / 128), 256, GEMM_SMEM>>>(b_enc);
    topk_h_kernel<<<M_, 256>>>();
    fixup_kernel<<<M_, 256>>>(x, b_enc, zsp);
    dec_kernel<<<dim3(M_, 2), 256>>>(W_dec, b_dec, recon);
}

// round 16
// speedup vs baseline: 1.1758x; 1.1758x over previous
#include <cuda_runtime.h>
#include <cuda_bf16.h>
#include <cuda_fp16.h>
#include <stdint.h>

constexpr int M_ = 4096;     // batch B
constexpr int K_ = 2048;     // D
constexpr int N_ = 16384;    // L
constexpr int TOPK = 64;
constexpr float MARGIN = 0.036f;  // > 2*(8*sigma_gemm + fp16 half-ulp) = 2*0.015
constexpr int CANDCAP = 192;

// ---------------- scratch (device globals; no allocs allowed) ----------------
__device__ __align__(256) __nv_bfloat16 g_xhi[M_ * K_];
__device__ __align__(256) __nv_bfloat16 g_whiT[(size_t)N_ * K_];  // W_enc^T bf16 [N,K]
__device__ __align__(256) float g_wT[(size_t)N_ * K_];            // W_enc^T fp32 [N,K]
__device__ __align__(256) __half g_zh[(size_t)M_ * N_];           // approx z, fp16
__device__ float g_topv[M_ * TOPK];
__device__ int   g_topi[M_ * TOPK];
__device__ int   g_cand[M_ * CANDCAP];   // idx | (above << 31)
__device__ int   g_ncand[M_];
__device__ int   g_nabove[M_];

// ---------------- helpers (family-safe ISA: sm_80/90 base) ----------------
__device__ __forceinline__ uint32_t smem_u32(const void* p) {
    uint32_t a;
    asm("{ .reg .u64 t; cvta.to.shared.u64 t, %1; cvt.u32.u64 %0, t; }" : "=r"(a) : "l"(p));
    return a;
}
__device__ __forceinline__ void cp_async16(uint32_t s, const void* g) {
    asm volatile("cp.async.cg.shared.global [%0], [%1], 16;" :: "r"(s), "l"(g));
}
__device__ __forceinline__ void ldmatrix4(uint32_t* r, uint32_t addr) {
    asm volatile("ldmatrix.sync.aligned.m8n8.x4.shared.b16 {%0,%1,%2,%3}, [%4];"
                 : "=r"(r[0]), "=r"(r[1]), "=r"(r[2]), "=r"(r[3]) : "r"(addr));
}
__device__ __forceinline__ void mma16816(float* d, const uint32_t* a, uint32_t b0, uint32_t b1) {
    asm volatile(
        "mma.sync.aligned.m16n8k16.row.col.f32.bf16.bf16.f32 "
        "{%0,%1,%2,%3}, {%4,%5,%6,%7}, {%8,%9}, {%0,%1,%2,%3};"
        : "+f"(d[0]), "+f"(d[1]), "+f"(d[2]), "+f"(d[3])
        : "r"(a[0]), "r"(a[1]), "r"(a[2]), "r"(a[3]), "r"(b0), "r"(b1));
}

// ---------------- conversion kernels ----------------
__global__ void __launch_bounds__(256) conv_x_kernel(const float* __restrict__ x) {
    int i = blockIdx.x * 256 + threadIdx.x;
    if (i < M_ * K_) g_xhi[i] = __float2bfloat16(x[i]);
}

// W_enc [K,N] -> transposed [N,K]: bf16 + fp32 copies
__global__ void __launch_bounds__(256) conv_w_kernel(const float* __restrict__ W) {
    __shared__ float t[32][33];
    const int tx = threadIdx.x, ty = threadIdx.y;   // 32 x 8
    const int n0 = blockIdx.x * 32, k0 = blockIdx.y * 32;
    #pragma unroll
    for (int j = 0; j < 4; j++)
        t[ty + j * 8][tx] = W[(size_t)(k0 + ty + j * 8) * N_ + (n0 + tx)];
    __syncthreads();
    #pragma unroll
    for (int j = 0; j < 4; j++) {
        float v = t[tx][ty + j * 8];
        size_t o = (size_t)(n0 + ty + j * 8) * K_ + (k0 + tx);
        g_whiT[o] = __float2bfloat16(v);
        g_wT[o] = v;
    }
}

// ---------------- bf16 encode GEMM: BK=64, 3-stage, ONE sync per chunk ----------------
// Epilogue also zeroes this tile's region of zsp (replaces the 268MB memset node).
constexpr int BK = 64;
constexpr int ROWB = 144;               // 64 bf16 = 128B + 16B pad (conflict-free ldmatrix)
constexpr int TILEB = 128 * ROWB;       // 18432 B
constexpr int STAGEB = 2 * TILEB;       // 36864 B (A+B)
constexpr int NSTAGE = 3;
constexpr int GEMM_SMEM = NSTAGE * STAGEB;   // 110592 B (2 CTAs/SM)

__global__ void __launch_bounds__(256, 2) enc_gemm_mma(const float* __restrict__ b_enc,
                                                       float* __restrict__ zsp) {
    extern __shared__ char sm[];
    const uint32_t base = smem_u32(sm);
    const int tid = threadIdx.x, lane = tid & 31, wid = tid >> 5;
    const int wm = wid & 3, wn = wid >> 2;          // 4x2 warp grid, warp tile 32x64
    const int row0 = blockIdx.x * 128;              // M tile
    const int col0 = blockIdx.y * 128;              // N tile

    float c[2][8][4];
    #pragma unroll
    for (int i = 0; i < 2; i++)
        #pragma unroll
        for (int j = 0; j < 8; j++)
            #pragma unroll
            for (int q = 0; q < 4; q++) c[i][j][q] = 0.f;

    auto issue = [&](int ch) {
        const int kk = ch * BK;
        const uint32_t st = base + (ch % NSTAGE) * STAGEB;
        #pragma unroll
        for (int j = 0; j < 4; j++) {
            const int slot = tid + 256 * j;         // 0..1023
            const int r = slot >> 3, cc = slot & 7; // 128 rows x 8 x 16B
            cp_async16(st + r * ROWB + cc * 16,
                       g_xhi + (size_t)(row0 + r) * K_ + kk + cc * 8);
            cp_async16(st + TILEB + r * ROWB + cc * 16,
                       g_whiT + (size_t)(col0 + r) * K_ + kk + cc * 8);
        }
        asm volatile("cp.async.commit_group;");
    };

    auto compute = [&](int s) {
        const uint32_t sa = base + s * STAGEB;
        const uint32_t sb = sa + TILEB;
        #pragma unroll
        for (int ks = 0; ks < 4; ks++) {
            uint32_t a[2][4];
            #pragma unroll
            for (int mi = 0; mi < 2; mi++) {
                const int row = wm * 32 + mi * 16 + (lane & 15);
                ldmatrix4(a[mi], sa + row * ROWB + ks * 32 + ((lane >> 4) << 4));
            }
            uint32_t b[4][4];
            #pragma unroll
            for (int nl = 0; nl < 4; nl++) {
                const int row = wn * 64 + nl * 16 + (lane & 7) + ((lane >> 4) << 3);
                ldmatrix4(b[nl], sb + row * ROWB + ks * 32 + (((lane >> 3) & 1) << 4));
            }
            #pragma unroll
            for (int mi = 0; mi < 2; mi++)
                #pragma unroll
                for (int nl = 0; nl < 4; nl++) {
                    mma16816(c[mi][2 * nl + 0], a[mi], b[nl][0], b[nl][1]);
                    mma16816(c[mi][2 * nl + 1], a[mi], b[nl][2], b[nl][3]);
                }
        }
    };

    constexpr int NCH = K_ / BK;        // 32
    issue(0); issue(1);                 // prologue: 2 chunks in flight
    for (int i = 0; i < NCH; i++) {
        asm volatile("cp.async.wait_group 1;");     // chunk i resident
        __syncthreads();                            // all warps done with stage (i-1)%3
        if (i + 2 < NCH) issue(i + 2);              // refill stage (i-1)%3
        else asm volatile("cp.async.commit_group;");// keep group-count math valid
        compute(i % NSTAGE);
    }

    const int gid = lane >> 2, tig = lane & 3;
    const float2 fz = make_float2(0.f, 0.f);
    #pragma unroll
    for (int mi = 0; mi < 2; mi++) {
        const int r0 = row0 + wm * 32 + mi * 16 + gid;
        #pragma unroll
        for (int ni = 0; ni < 8; ni++) {
            const int cc = col0 + wn * 64 + ni * 8 + 2 * tig;
            const float2 bb = *(const float2*)(b_enc + cc);
            __half2 h0 = __floats2half2_rn(c[mi][ni][0] + bb.x, c[mi][ni][1] + bb.y);
            __half2 h1 = __floats2half2_rn(c[mi][ni][2] + bb.x, c[mi][ni][3] + bb.y);
            *(__half2*)(g_zh + (size_t)r0 * N_ + cc) = h0;
            *(__half2*)(g_zh + (size_t)(r0 + 8) * N_ + cc) = h1;
            // zero-init the fp32 z_sparse output for this tile (memset replacement)
            *(float2*)(zsp + (size_t)r0 * N_ + cc) = fz;
            *(float2*)(zsp + (size_t)(r0 + 8) * N_ + cc) = fz;
        }
    }
}

// ---------------- top-k on fp16 keys: 2-pass radix + candidate emit ----------------
__global__ void __launch_bounds__(256) topk_h_kernel() {
    __shared__ uint32_t skey[N_ / 2];        // 8192 words, 2 keys each (32KB)
    __shared__ int hist[8][256];             // per-warp histograms (8KB)
    __shared__ int s_h1[256];
    __shared__ int s_b, s_r, s_T;
    __shared__ int s_nc, s_na;

    const int row = blockIdx.x;
    const int tid = threadIdx.x, wid = tid >> 5;

    for (int b = tid; b < 8 * 256; b += 256) ((int*)hist)[b] = 0;
    if (tid == 0) { s_nc = 0; s_na = 0; }
    __syncthreads();

    // pass 0: load row (2048 uint4), pack 15-bit keys, hist on top 8 bits
    const uint4* zr = (const uint4*)(g_zh + (size_t)row * N_);
    #pragma unroll
    for (int it = 0; it < 8; it++) {
        const int i4 = tid + it * 256;        // uint4 index: 8 fp16 each
        uint4 v = zr[i4];
        uint32_t wv[4] = { v.x, v.y, v.z, v.w };
        #pragma unroll
        for (int q = 0; q < 4; q++) {
            uint32_t lo = wv[q] & 0x7FFFu;
            uint32_t hi = (wv[q] >> 16) & 0x7FFFu;
            skey[i4 * 4 + q] = lo | (hi << 16);   // word w holds elements 2w, 2w+1
            atomicAdd(&hist[wid][lo >> 7], 1);
            atomicAdd(&hist[wid][hi >> 7], 1);
        }
    }
    __syncthreads();
    {
        int tot = 0;
        #pragma unroll
        for (int w = 0; w < 8; w++) tot += hist[w][tid];
        s_h1[tid] = tot;
    }
    __syncthreads();
    if (tid == 0) {
        int r = TOPK, b = 255;
        for (; b > 0; b--) { int cnt = s_h1[b]; if (cnt >= r) break; r -= cnt; }
        s_b = b; s_r = r;
    }
    __syncthreads();
    const int bsel = s_b;

    // pass 1: hist on low 7 bits within bucket bsel (all 8192 words)
    for (int b = tid; b < 8 * 256; b += 256) ((int*)hist)[b] = 0;
    __syncthreads();
    #pragma unroll
    for (int it = 0; it < 32; it++) {
        const int iw = tid + it * 256;        // 0..8191
        uint32_t pk = skey[iw];
        uint32_t lo = pk & 0xFFFFu, hi = pk >> 16;
        if ((int)(lo >> 7) == bsel) atomicAdd(&hist[wid][lo & 127u], 1);
        if ((int)(hi >> 7) == bsel) atomicAdd(&hist[wid][hi & 127u], 1);
    }
    __syncthreads();
    if (tid < 128) {
        int tot = 0;
        #pragma unroll
        for (int w = 0; w < 8; w++) tot += hist[w][tid];
        s_h1[tid] = tot;
    }
    __syncthreads();
    if (tid == 0) {
        int r = s_r, m = 127;
        for (; m > 0; m--) { int cnt = s_h1[m]; if (cnt >= r) break; r -= cnt; }
        s_T = (bsel << 7) | m;
    }
    __syncthreads();

    // fp16 threshold bits -> float (exact)
    __half_raw traw; traw.x = (unsigned short)s_T;
    const float tval = __half2float(__half(traw));
    const float blo = tval - MARGIN, bhi = tval + MARGIN;

    // pass 2: count above-band, emit candidates (|z| >= blo) over all 8192 words
    int myabove = 0;
    #pragma unroll
    for (int it = 0; it < 32; it++) {
        const int iw = tid + it * 256;        // 0..8191
        uint32_t pk = skey[iw];
        #pragma unroll
        for (int h = 0; h < 2; h++) {
            uint32_t key = h ? (pk >> 16) : (pk & 0xFFFFu);
            __half_raw kr; kr.x = (unsigned short)key;
            float av = __half2float(__half(kr));
            if (av >= blo) {
                bool above = (av > bhi);
                myabove += above ? 1 : 0;
                int p = atomicAdd(&s_nc, 1);
                if (p < CANDCAP)
                    g_cand[row * CANDCAP + p] = (iw * 2 + h) | (above ? 0x80000000 : 0);
            }
        }
    }
    atomicAdd(&s_na, myabove);
    __syncthreads();
    if (tid == 0) {
        g_ncand[row] = min(s_nc, CANDCAP);
        g_nabove[row] = s_na;
    }
}

// ---------------- exact fixup: fp32 dots, exact re-rank, scatter into zeroed z ----------------
__global__ void __launch_bounds__(256) fixup_kernel(
    const float* __restrict__ x, const float* __restrict__ b_enc,
    float* __restrict__ z) {
    __shared__ float sx[K_];
    __shared__ int   s_idx[CANDCAP];
    __shared__ float s_val[CANDCAP];
    __shared__ unsigned char s_abv[CANDCAP];
    __shared__ unsigned char s_keep[CANDCAP];

    const int row = blockIdx.x;
    const int tid = threadIdx.x, lid = tid & 31, wrp = tid >> 5;
    const int nc = g_ncand[row];
    const int slots = TOPK - g_nabove[row];

    for (int i = tid; i < K_; i += 256) sx[i] = x[(size_t)row * K_ + i];
    if (tid < nc) {
        int e = g_cand[row * CANDCAP + tid];
        s_idx[tid] = e & 0x7FFFFFFF;
        s_abv[tid] = (e >> 31) & 1;
        s_keep[tid] = 0;
    }
    __syncthreads();

    // exact fp32 dots against coalesced g_wT rows
    for (int c = wrp; c < nc; c += 8) {
        const int j = s_idx[c];
        const float* wr = g_wT + (size_t)j * K_;
        float a0 = 0.f, a1 = 0.f, a2 = 0.f, a3 = 0.f;
        for (int k = lid; k < K_; k += 128) {
            a0 = fmaf(sx[k],      wr[k],      a0);
            a1 = fmaf(sx[k + 32], wr[k + 32], a1);
            a2 = fmaf(sx[k + 64], wr[k + 64], a2);
            a3 = fmaf(sx[k + 96], wr[k + 96], a3);
        }
        float acc = (a0 + a1) + (a2 + a3);
        #pragma unroll
        for (int o = 16; o; o >>= 1) acc += __shfl_xor_sync(0xFFFFFFFFu, acc, o);
        if (lid == 0) s_val[c] = acc + b_enc[j];
    }
    __syncthreads();

    // keep: all above-band + top-`slots` band members by (|exact|, idx)
    if (tid < nc) {
        if (s_abv[tid]) {
            s_keep[tid] = 1;
        } else {
            const float mv = fabsf(s_val[tid]);
            const int mi = s_idx[tid];
            int rank = 0;
            for (int f = 0; f < nc; f++) {
                if (s_abv[f] || f == tid) continue;
                const float fv = fabsf(s_val[f]);
                if (fv > mv || (fv == mv && s_idx[f] < mi)) rank++;
            }
            s_keep[tid] = (rank < slots) ? 1 : 0;
        }
    }
    __syncthreads();

    // scatter exact kept values into zeroed z + final compact lists (index-ascending)
    float* zrow = z + (size_t)row * N_;
    if (tid < nc && s_keep[tid]) {
        const int mi = s_idx[tid];
        zrow[mi] = s_val[tid];
        int pos = 0;
        for (int f = 0; f < nc; f++)
            if (s_keep[f] && s_idx[f] < mi) pos++;
        if (pos < TOPK) {
            g_topv[row * TOPK + pos] = s_val[tid];
            g_topi[row * TOPK + pos] = mi;
        }
    }
}

// ---------------- sparse decode: 2 CTAs per row (half-row each) ----------------
__global__ void __launch_bounds__(256) dec_kernel(
    const float* __restrict__ Wd, const float* __restrict__ bd,
    float* __restrict__ recon) {
    __shared__ float sv[TOPK];
    __shared__ int   si[TOPK];
    const int row = blockIdx.x;
    const int tid = threadIdx.x;
    if (tid < TOPK) { sv[tid] = g_topv[row * TOPK + tid]; si[tid] = g_topi[row * TOPK + tid]; }
    __syncthreads();

    const int c0 = blockIdx.y * 1024 + tid * 4;   // this CTA's half-row column
    float4 a0 = *(const float4*)(bd + c0);
    #pragma unroll 4
    for (int j = 0; j < TOPK; j += 4) {
        const float v0 = sv[j], v1 = sv[j + 1], v2 = sv[j + 2], v3 = sv[j + 3];
        float4 w0 = *(const float4*)(Wd + (size_t)si[j] * 2048 + c0);
        float4 w1 = *(const float4*)(Wd + (size_t)si[j + 1] * 2048 + c0);
        float4 w2 = *(const float4*)(Wd + (size_t)si[j + 2] * 2048 + c0);
        float4 w3 = *(const float4*)(Wd + (size_t)si[j + 3] * 2048 + c0);
        a0.x += v0 * w0.x; a0.y += v0 * w0.y; a0.z += v0 * w0.z; a0.w += v0 * w0.w;
        a0.x += v1 * w1.x; a0.y += v1 * w1.y; a0.z += v1 * w1.z; a0.w += v1 * w1.w;
        a0.x += v2 * w2.x; a0.y += v2 * w2.y; a0.z += v2 * w2.z; a0.w += v2 * w2.w;
        a0.x += v3 * w3.x; a0.y += v3 * w3.y; a0.z += v3 * w3.z; a0.w += v3 * w3.w;
    }
    *(float4*)(recon + (size_t)row * 2048 + c0) = a0;
}

// ---------------- launch ----------------
extern "C" void kernel_launch(void* const* d_in, const int* in_sizes, int n_in,
                              void* d_out, int out_size) {
    const float* x     = (const float*)d_in[0];
    const float* W_enc = (const float*)d_in[1];
    const float* b_enc = (const float*)d_in[2];
    const float* W_dec = (const float*)d_in[3];
    const float* b_dec = (const float*)d_in[4];

    float* recon = (float*)d_out;
    float* zsp   = (float*)d_out + (size_t)M_ * 2048;

    cudaFuncSetAttribute(enc_gemm_mma, cudaFuncAttributeMaxDynamicSharedMemorySize, GEMM_SMEM);

    conv_x_kernel<<<(M_ * K_ + 255) / 256, 256>>>(x);
    conv_w_kernel<<<dim3(N_ / 32, K_ / 32), dim3(32, 8)>>>(W_enc);
    enc_gemm_mma<<<dim3(M_ / 128, N_ / 128), 256, GEMM_SMEM>>>(b_enc, zsp);
    topk_h_kernel<<<M_, 256>>>();
    fixup_kernel<<<M_, 256>>>(x, b_enc, zsp);
    dec_kernel<<<dim3(M_, 2), 256>>>(W_dec, b_dec, recon);
}